// round 11
// baseline (speedup 1.0000x reference)
#include <cuda_runtime.h>

#define TLEN  640
#define DDIM  256
#define NH    64              // distinct harmonics (D / NUM_CH)
#define NWARP 8
#define NT    (TLEN / NWARP)  // 80 samples per warp chunk

typedef unsigned long long u64;

__device__ __forceinline__ u64 pk2(float lo, float hi) {
    u64 r; asm("mov.b64 %0, {%1,%2};" : "=l"(r) : "f"(lo), "f"(hi)); return r;
}
__device__ __forceinline__ void upk2(u64 v, float &lo, float &hi) {
    asm("mov.b64 {%0,%1}, %2;" : "=f"(lo), "=f"(hi) : "l"(v));
}
__device__ __forceinline__ u64 fma2(u64 a, u64 b, u64 c) {
    u64 d; asm("fma.rn.f32x2 %0, %1, %2, %3;" : "=l"(d) : "l"(a), "l"(b), "l"(c)); return d;
}

#define INV2PI 0.15915494309189535f
#define PI2_HI 6.28125f                    // 8-bit mantissa: k*PI2_HI exact for k small
#define PI2_LO 1.9353071795864769e-3f
#define T_WAV  6.25e-05f                   // fl(1/16000), matches reference arange*scalar

// fast mod-2pi + MUFU sincos
__device__ __forceinline__ void fast_sincos_r(float x, float *s, float *c) {
    const float k = rintf(x * INV2PI);
    float r = __fmaf_rn(-k, PI2_HI, x);
    r = __fmaf_rn(-k, PI2_LO, r);
    __sincosf(r, s, c);
}

// Goertzel per (t-chunk, harmonic):  s_n = x_n + 2cos(d)*s_{n-1} - s_{n-2}
// y = s_{N-1} - e^{-id} s_{N-2};  C + iS = e^{i psi_last} * conj(y)
// out[sb,dd] = a[dd] * ( cos(phi)*S_h + sin(phi)*C_h ),  h = dd>>2
//
// R9 structure (per-thread fp32 seeds overlapping x staging, registers live
// across the loop) + 7-CTA/SM cap so the 1024-CTA grid is ONE wave, and
// float4 main-loop loads (half the LDS instruction count).
__global__ __launch_bounds__(256, 7) void sinenet_kernel(
    const float* __restrict__ x,   const float* __restrict__ nlf,
    const float* __restrict__ tau, const float* __restrict__ a,
    const float* __restrict__ phi, const float* __restrict__ i2pi,
    const float* __restrict__ kT,  float* __restrict__ out)
{
    __shared__ __align__(16) float xs[TLEN];
    __shared__ float partS[NWARP][NH], partC[NWARP][NH];

    const int sb  = blockIdx.x;
    const int tid = threadIdx.x;
    const int w   = tid >> 5;
    const int l   = tid & 31;

    // stage x[sb,:] (160 float4 loads; issued first, overlapped by seed math)
    if (tid < TLEN / 4) {
        const float4 v = reinterpret_cast<const float4*>(x + sb * TLEN)[tid];
        reinterpret_cast<float4*>(xs)[tid] = v;
    }

    // ---- per-thread seeds, all fp32, no shared ----
    const float fF   = expf(__fadd_rn(__fmul_rn(nlf[sb], 0.373288f), 5.02654f));
    const float tv   = tau[sb];
    const float om1  = __fmul_rn(i2pi[0], fF);
    const float tshL = __fadd_rn(__fmul_rn((float)(w * NT + (NT - 1)), T_WAV), -tv);

    // base = om1*tshL mod 2pi as hi/lo pair (exact product split + Cody-Waite)
    float bHi, bLo;
    {
        const float p  = __fmul_rn(om1, tshL);
        const float pe = __fmaf_rn(om1, tshL, -p);        // exact low part
        const float k  = rintf(p * INV2PI);
        float r = __fmaf_rn(-k, PI2_HI, p);
        r = __fmaf_rn(-k, PI2_LO, r);
        bHi = r;  bLo = pe;
    }

    float cd[2], sd[2], ce[2], se[2];
    #pragma unroll
    for (int q = 0; q < 2; ++q) {
        const int   h   = l + 32 * q;
        const float Hf  = (float)(h + 1);
        const float omg = __fmul_rn(i2pi[4 * h], fF);     // bit-matches ref's i_f
        fast_sincos_r(omg * T_WAV, &sd[q], &cd[q]);       // delta = omg/16000
        const float eps = __fmaf_rn(-Hf, om1, omg);       // exact residual
        // psi = Hf*(bHi+bLo) + eps*tshL, Cody-Waite reduced mod 2pi
        const float p   = Hf * bHi;
        const float pe  = __fmaf_rn(Hf, bHi, -p);         // exact low part
        const float plo = __fmaf_rn(Hf, bLo, __fmaf_rn(eps, tshL, pe));
        const float k   = rintf(p * INV2PI);
        float r = __fmaf_rn(-k, PI2_HI, p);
        r = __fmaf_rn(-k, PI2_LO, r) + plo;
        __sincosf(r, &se[q], &ce[q]);
    }

    const u64 twoC = pk2(cd[0] + cd[0], cd[1] + cd[1]);
    const u64 nOne = pk2(-1.0f, -1.0f);
    u64 s1 = 0ull, s2 = 0ull;

    __syncthreads();   // xs ready

    // main loop: 1 LDS.128 + 4 reg-packs + 8 packed fma per 4 samples
    const float4* xp = reinterpret_cast<const float4*>(xs + w * NT);
    #pragma unroll 5
    for (int j = 0; j < NT / 4; ++j) {
        const float4 xv = xp[j];
        {   const u64 xa = pk2(xv.x, xv.x);
            const u64 t0 = fma2(nOne, s2, xa);
            const u64 n0 = fma2(twoC, s1, t0);  s2 = s1; s1 = n0; }
        {   const u64 xa = pk2(xv.y, xv.y);
            const u64 t0 = fma2(nOne, s2, xa);
            const u64 n0 = fma2(twoC, s1, t0);  s2 = s1; s1 = n0; }
        {   const u64 xa = pk2(xv.z, xv.z);
            const u64 t0 = fma2(nOne, s2, xa);
            const u64 n0 = fma2(twoC, s1, t0);  s2 = s1; s1 = n0; }
        {   const u64 xa = pk2(xv.w, xv.w);
            const u64 t0 = fma2(nOne, s2, xa);
            const u64 n0 = fma2(twoC, s1, t0);  s2 = s1; s1 = n0; }
    }

    // per-chain extraction: y = s1 - e^{-id} s2, rotate conj(y) by psi_last
    float A0, A1, B0, B1;
    upk2(s1, A0, A1);
    upk2(s2, B0, B1);
    {
        const float Re = __fmaf_rn(-cd[0], B0, A0);
        const float Im = sd[0] * B0;
        partS[w][l] = se[0] * Re - ce[0] * Im;
        partC[w][l] = ce[0] * Re + se[0] * Im;
    }
    {
        const float Re = __fmaf_rn(-cd[1], B1, A1);
        const float Im = sd[1] * B1;
        partS[w][l + 32] = se[1] * Re - ce[1] * Im;
        partC[w][l + 32] = ce[1] * Re + se[1] * Im;
    }
    __syncthreads();

    // fused reduce + epilogue: 64 threads, one harmonic each -> float4 out
    if (tid < NH) {
        const int h = tid;
        float Ss = 0.0f, Cs = 0.0f;
        #pragma unroll
        for (int ww = 0; ww < NWARP; ++ww) {
            Ss += partS[ww][h];
            Cs += partC[ww][h];
        }
        const float4 a4 = reinterpret_cast<const float4*>(a)[h];
        const float4 p4 = reinterpret_cast<const float4*>(phi)[h];
        float4 o;
        float sph, cph;
        __sincosf(p4.x, &sph, &cph);  o.x = a4.x * (cph * Ss + sph * Cs);
        __sincosf(p4.y, &sph, &cph);  o.y = a4.y * (cph * Ss + sph * Cs);
        __sincosf(p4.z, &sph, &cph);  o.z = a4.z * (cph * Ss + sph * Cs);
        __sincosf(p4.w, &sph, &cph);  o.w = a4.w * (cph * Ss + sph * Cs);
        reinterpret_cast<float4*>(out + sb * DDIM)[h] = o;
    }
}

extern "C" void kernel_launch(void* const* d_in, const int* in_sizes, int n_in,
                              void* d_out, int out_size)
{
    const float* x    = (const float*)d_in[0];   // (S,B,1,T)
    const float* nlf  = (const float*)d_in[1];   // (S,B,1,1)
    const float* tau  = (const float*)d_in[2];   // (S,B,1,1)
    const float* a    = (const float*)d_in[3];   // (D,1)
    const float* phi  = (const float*)d_in[4];   // (D,1)
    const float* i2pi = (const float*)d_in[5];   // (D,1)
    const float* kT   = (const float*)d_in[6];   // (1,T)
    float* out = (float*)d_out;                  // (S,B,D)

    sinenet_kernel<<<1024, 256>>>(x, nlf, tau, a, phi, i2pi, kT, out);
}

// round 12
// speedup vs baseline: 1.0263x; 1.0263x over previous
#include <cuda_runtime.h>

#define TLEN  640
#define DDIM  256
#define NH    64              // distinct harmonics (D / NUM_CH)
#define NWARP 8               // warps per block; each warp owns one (s,b)
#define NG    (TLEN / 4)      // 160 4-sample groups per warp

typedef unsigned long long u64;

__device__ __forceinline__ u64 pk2(float lo, float hi) {
    u64 r; asm("mov.b64 %0, {%1,%2};" : "=l"(r) : "f"(lo), "f"(hi)); return r;
}
__device__ __forceinline__ void upk2(u64 v, float &lo, float &hi) {
    asm("mov.b64 {%0,%1}, %2;" : "=f"(lo), "=f"(hi) : "l"(v));
}
__device__ __forceinline__ u64 fma2(u64 a, u64 b, u64 c) {
    u64 d; asm("fma.rn.f32x2 %0, %1, %2, %3;" : "=l"(d) : "l"(a), "l"(b), "l"(c)); return d;
}

#define INV2PI 0.15915494309189535f
#define PI2_HI 6.28125f                    // 8-bit mantissa: k*PI2_HI exact for k small
#define PI2_LO 1.9353071795864769e-3f
#define T_WAV  6.25e-05f                   // fl(1/16000), matches reference arange*scalar

// fast mod-2pi + MUFU sincos
__device__ __forceinline__ void fast_sincos_r(float x, float *s, float *c) {
    const float k = rintf(x * INV2PI);
    float r = __fmaf_rn(-k, PI2_HI, x);
    r = __fmaf_rn(-k, PI2_LO, r);
    __sincosf(r, s, c);
}

// One warp per (s,b). Lane l covers harmonics h=l and h=l+32 (packed f32x2).
// 4-way decimated Goertzel: chain c in {0..3} processes samples t=4u+c at
// angle D=4*delta (160 steps, 4 independent chains for ILP at low occupancy).
// Per chain: y_c = s1 - e^{-iD} s2;  z_c = conj(y_c).
// C + iS = e^{i psi3} * [((z0 e^{-i d} + z1) e^{-i d} + z2) e^{-i d} + z3],
// psi3 = omega*(t639*T_WAV - tau) mod 2pi.
// out[sb,dd] = a[dd] * ( cos(phi)*S_h + sin(phi)*C_h ),  h = dd>>2
// NO __syncthreads anywhere: staging, compute, reduce, output all in-warp.
__global__ __launch_bounds__(256) void sinenet_kernel(
    const float* __restrict__ x,   const float* __restrict__ nlf,
    const float* __restrict__ tau, const float* __restrict__ a,
    const float* __restrict__ phi, const float* __restrict__ i2pi,
    const float* __restrict__ kT,  float* __restrict__ out)
{
    __shared__ __align__(16) float xs[NWARP][TLEN];

    const int tid = threadIdx.x;
    const int w   = tid >> 5;
    const int l   = tid & 31;
    const int sb  = blockIdx.x * NWARP + w;

    // stage this warp's x[sb,:]: 5 coalesced float4 loads per lane
    {
        const float4* xg4 = reinterpret_cast<const float4*>(x + sb * TLEN);
        float4* xs4 = reinterpret_cast<float4*>(xs[w]);
        #pragma unroll
        for (int k = 0; k < 5; ++k) {
            const int i = l + 32 * k;
            xs4[i] = xg4[i];
        }
    }

    // ---- per-thread seeds, all fp32 (overlap the staging LDG latency) ----
    const float fF   = expf(__fadd_rn(__fmul_rn(nlf[sb], 0.373288f), 5.02654f));
    const float tv   = tau[sb];
    const float om1  = __fmul_rn(i2pi[0], fF);
    const float tshL = __fadd_rn(__fmul_rn(639.0f, T_WAV), -tv);  // t index 639

    // base = om1*tshL mod 2pi as hi/lo pair (exact product split + Cody-Waite)
    float bHi, bLo;
    {
        const float p  = __fmul_rn(om1, tshL);
        const float pe = __fmaf_rn(om1, tshL, -p);
        const float k  = rintf(p * INV2PI);
        float r = __fmaf_rn(-k, PI2_HI, p);
        r = __fmaf_rn(-k, PI2_LO, r);
        bHi = r;  bLo = pe;
    }

    float cd[2], sd[2], cD[2], sD[2], ce[2], se[2];
    #pragma unroll
    for (int q = 0; q < 2; ++q) {
        const int   h   = l + 32 * q;
        const float Hf  = (float)(h + 1);
        const float omg = __fmul_rn(i2pi[4 * h], fF);     // bit-matches ref's i_f
        const float dlt = omg * T_WAV;
        fast_sincos_r(dlt, &sd[q], &cd[q]);               // per-sample step
        fast_sincos_r(4.0f * dlt, &sD[q], &cD[q]);        // chain angle 4*delta
        const float eps = __fmaf_rn(-Hf, om1, omg);       // exact residual
        // psi3 = Hf*(bHi+bLo) + eps*tshL, Cody-Waite reduced mod 2pi
        const float p   = Hf * bHi;
        const float pe  = __fmaf_rn(Hf, bHi, -p);
        const float plo = __fmaf_rn(Hf, bLo, __fmaf_rn(eps, tshL, pe));
        const float k   = rintf(p * INV2PI);
        float r = __fmaf_rn(-k, PI2_HI, p);
        r = __fmaf_rn(-k, PI2_LO, r) + plo;
        __sincosf(r, &se[q], &ce[q]);
    }

    const u64 twoC = pk2(cD[0] + cD[0], cD[1] + cD[1]);
    const u64 nOne = pk2(-1.0f, -1.0f);
    u64 a1 = 0ull, A2 = 0ull;   // chain 0 (samples 4u+0)
    u64 b1 = 0ull, b2 = 0ull;   // chain 1
    u64 c1 = 0ull, c2 = 0ull;   // chain 2
    u64 d1 = 0ull, d2 = 0ull;   // chain 3

    __syncwarp();   // staging visible within the warp

    // main loop: 1 LDS.128 + 4 packs + 8 FFMA2 per 4 samples; 4 indep chains
    const float4* xp = reinterpret_cast<const float4*>(xs[w]);
    #pragma unroll 4
    for (int u = 0; u < NG; ++u) {
        const float4 xv = xp[u];
        {   const u64 xq = pk2(xv.x, xv.x);
            const u64 t = fma2(nOne, A2, xq);
            const u64 n = fma2(twoC, a1, t);  A2 = a1; a1 = n; }
        {   const u64 xq = pk2(xv.y, xv.y);
            const u64 t = fma2(nOne, b2, xq);
            const u64 n = fma2(twoC, b1, t);  b2 = b1; b1 = n; }
        {   const u64 xq = pk2(xv.z, xv.z);
            const u64 t = fma2(nOne, c2, xq);
            const u64 n = fma2(twoC, c1, t);  c2 = c1; c1 = n; }
        {   const u64 xq = pk2(xv.w, xv.w);
            const u64 t = fma2(nOne, d2, xq);
            const u64 n = fma2(twoC, d1, t);  d2 = d1; d1 = n; }
    }

    // extraction + in-warp combine + epilogue
    float s1f[4][2], s2f[4][2];
    upk2(a1, s1f[0][0], s1f[0][1]);  upk2(A2, s2f[0][0], s2f[0][1]);
    upk2(b1, s1f[1][0], s1f[1][1]);  upk2(b2, s2f[1][0], s2f[1][1]);
    upk2(c1, s1f[2][0], s1f[2][1]);  upk2(c2, s2f[2][0], s2f[2][1]);
    upk2(d1, s1f[3][0], s1f[3][1]);  upk2(d2, s2f[3][0], s2f[3][1]);

    #pragma unroll
    for (int q = 0; q < 2; ++q) {
        // z_c = conj(y_c): zR = s1 - cos(D)*s2, zI = -sin(D)*s2
        float accR = 0.0f, accI = 0.0f;
        #pragma unroll
        for (int c = 0; c < 4; ++c) {
            const float zR = __fmaf_rn(-cD[q], s2f[c][q], s1f[c][q]);
            const float zI = -sD[q] * s2f[c][q];
            if (c == 0) { accR = zR; accI = zI; }
            else {
                // acc *= e^{-i delta}; acc += z_c
                const float nR = __fmaf_rn(accR, cd[q],  accI * sd[q]);
                const float nI = __fmaf_rn(accI, cd[q], -accR * sd[q]);
                accR = nR + zR;
                accI = nI + zI;
            }
        }
        // C + iS = e^{i psi3} * acc
        const float C = __fmaf_rn(ce[q], accR, -se[q] * accI);
        const float S = __fmaf_rn(se[q], accR,  ce[q] * accI);

        const int h = l + 32 * q;
        const float4 a4 = reinterpret_cast<const float4*>(a)[h];
        const float4 p4 = reinterpret_cast<const float4*>(phi)[h];
        float4 o;
        float sph, cph;
        __sincosf(p4.x, &sph, &cph);  o.x = a4.x * (cph * S + sph * C);
        __sincosf(p4.y, &sph, &cph);  o.y = a4.y * (cph * S + sph * C);
        __sincosf(p4.z, &sph, &cph);  o.z = a4.z * (cph * S + sph * C);
        __sincosf(p4.w, &sph, &cph);  o.w = a4.w * (cph * S + sph * C);
        reinterpret_cast<float4*>(out + sb * DDIM)[h] = o;
    }
}

extern "C" void kernel_launch(void* const* d_in, const int* in_sizes, int n_in,
                              void* d_out, int out_size)
{
    const float* x    = (const float*)d_in[0];   // (S,B,1,T)
    const float* nlf  = (const float*)d_in[1];   // (S,B,1,1)
    const float* tau  = (const float*)d_in[2];   // (S,B,1,1)
    const float* a    = (const float*)d_in[3];   // (D,1)
    const float* phi  = (const float*)d_in[4];   // (D,1)
    const float* i2pi = (const float*)d_in[5];   // (D,1)
    const float* kT   = (const float*)d_in[6];   // (1,T)
    float* out = (float*)d_out;                  // (S,B,D)

    sinenet_kernel<<<128, 256>>>(x, nlf, tau, a, phi, i2pi, kT, out);
}